// round 4
// baseline (speedup 1.0000x reference)
#include <cuda_runtime.h>
#include <cuda_bf16.h>

// ---------------------------------------------------------------------------
// Weight table: wblk[(ds1*3+ds2)*27 + (dh1*9+dw1*3+dh2)] is a 4-slot row of
// float2 (k, k') pairs for dw2 = 0,1,2 (slot 3 = pad for 32B alignment).
// ---------------------------------------------------------------------------
__device__ float2 g_wblk[243 * 4];

__global__ void prep_kernel(const float* __restrict__ kern) {
    int i = blockIdx.x * blockDim.x + threadIdx.x;
    if (i >= 729) return;
    int b   = i / 3;        // 0..242
    int dw2 = i % 3;
    int ds  = b / 27;
    int r   = b % 27;
    int dh1 = r / 9, dw1 = (r / 3) % 3, dh2 = r % 3;
    int ds1 = ds / 3, ds2 = ds % 3;
    float k  = kern[((((ds1*3 + ds2)*3 + dh1)*3 + dw1)*3 + dh2)*3 + dw2];
    float kt = kern[((((ds2*3 + ds1)*3 + dh2)*3 + dw2)*3 + dh1)*3 + dw1];
    g_wblk[b * 4 + dw2] = make_float2(k, kt);
}

// ---------------------------------------------------------------------------
// Main conv kernel.
// Tile per block: (h1,w1,h2,w2) = (4,4,8,8) = 1024 points, 128 threads,
// each thread computes the full w2 row (8 points) x 4 s_out x 2 kernels.
// Shared: 4 relu'd halo planes [6][6][10][12-pad] (69120 B) + weight table
// (7776 B) = 76896 B -> 3 CTAs/SM.
// ---------------------------------------------------------------------------
#define PLANE_F   4320                     // 6*6*10*12 floats
#define SMEM_F    (4 * PLANE_F)            // 17280 floats
#define SMEM_BYTES (SMEM_F * 4 + 243*4*8)  // 69120 + 7776 = 76896

__global__ __launch_bounds__(128, 3)
void conv_kernel(const float* __restrict__ x, float* __restrict__ out) {
    extern __shared__ float sm[];
    float2* wsm = (float2*)(sm + SMEM_F);

    const int tid = threadIdx.x;
    const int bid = blockIdx.x;
    const int bw2 = bid & 3;          // w2 tile (of 4)
    const int bh2 = (bid >> 2) & 3;   // h2 tile (of 4)
    const int bw1 = (bid >> 4) & 7;   // w1 tile (of 8)
    const int bh1 = bid >> 7;         // h1 tile (of 8)

    const int H1o = bh1 * 4 - 1, W1o = bw1 * 4 - 1;
    const int H2o = bh2 * 8 - 1, W2o = bw2 * 8 - 1;

    // ---- Load phase: 4 halo planes, relu'd, zero-padded at boundaries. ----
    // 144 rows of (s,a1,a2); each thread owns one (a3,a4) cell: a3*12+a4 = tid.
    {
        const int a3 = tid / 12;             // 0..10 (tid<120 valid)
        const int a4 = tid - a3 * 12;
        const int g3 = H2o + a3, g4 = W2o + a4;
        const bool ok34 = ((unsigned)g3 < 32u) && ((unsigned)g4 < 32u) && (tid < 120);
        const int t34 = g3 * 32 + g4;
        if (tid < 120) {
#pragma unroll 4
            for (int row = 0; row < 144; row++) {
                int s  = row / 36;
                int a1 = (row / 6) % 6;
                int a2 = row % 6;
                int g1 = H1o + a1, g2 = W1o + a2;
                bool ok = ok34 && ((unsigned)g1 < 32u) && ((unsigned)g2 < 32u);
                float v = 0.0f;
                if (ok) v = fmaxf(x[s * 1048576 + g1 * 32768 + g2 * 1024 + t34], 0.0f);
                sm[s * PLANE_F + (a1 * 6 + a2) * 120 + tid] = v;
            }
        }
        for (int i = tid; i < 972; i += 128) wsm[i] = g_wblk[i];
    }
    __syncthreads();

    // ---- Thread -> output coords within tile ----
    const int h1 = tid >> 5;
    const int w1 = (tid >> 3) & 3;
    const int h2 = tid & 7;
    const int trow = ((h1 * 6 + w1) * 10 + h2) * 12;

    // acc[p][so][krn]: 64 independent accumulator chains
    float acc[8][4][2];
#pragma unroll
    for (int p = 0; p < 8; p++)
#pragma unroll
        for (int so = 0; so < 4; so++) { acc[p][so][0] = 0.0f; acc[p][so][1] = 0.0f; }

#pragma unroll 1
    for (int s_in = 0; s_in < 4; s_in++) {
        const float* base = sm + s_in * PLANE_F + trow;
        const int s1i = s_in >> 1, s2i = s_in & 1;
        const float2* wb[4];
#pragma unroll
        for (int so = 0; so < 4; so++) {
            int ds1 = s1i - (so >> 1) + 1;
            int ds2 = s2i - (so & 1) + 1;
            wb[so] = wsm + (ds1 * 3 + ds2) * 108;   // 27 groups * 4 slots
        }
#pragma unroll 1
        for (int dh1 = 0; dh1 < 3; dh1++) {
#pragma unroll
            for (int dw1 = 0; dw1 < 3; dw1++) {
#pragma unroll
                for (int dh2 = 0; dh2 < 3; dh2++) {
                    const float* row = base + dh1 * 720 + dw1 * 120 + dh2 * 12;
                    float4 va = *(const float4*)row;
                    float4 vbq = *(const float4*)(row + 4);
                    float2 vc = *(const float2*)(row + 8);
                    float xv[10] = {va.x, va.y, va.z, va.w,
                                    vbq.x, vbq.y, vbq.z, vbq.w,
                                    vc.x, vc.y};
                    const int gidx = (dh1 * 9 + dw1 * 3 + dh2) * 4;
#pragma unroll
                    for (int so = 0; so < 4; so++) {
                        float4 w01 = *(const float4*)(wb[so] + gidx);      // dw2=0,1
                        float2 w2p = *(const float2*)(wb[so] + gidx + 2);  // dw2=2
#pragma unroll
                        for (int p = 0; p < 8; p++) {
                            acc[p][so][0] += w01.x * xv[p];
                            acc[p][so][1] += w01.y * xv[p];
                            acc[p][so][0] += w01.z * xv[p + 1];
                            acc[p][so][1] += w01.w * xv[p + 1];
                            acc[p][so][0] += w2p.x * xv[p + 2];
                            acc[p][so][1] += w2p.y * xv[p + 2];
                        }
                    }
                }
            }
        }
    }

    // ---- Epilogue: sigmoid both branches, mask by (x != 0), sum over s_out ----
    const int H1 = bh1 * 4 + h1, W1 = bw1 * 4 + w1;
    const int H2 = bh2 * 8 + h2, W2 = bw2 * 8;
    const int base_sp = ((H1 * 32 + W1) * 32 + H2) * 32 + W2;

    float res[8];
#pragma unroll
    for (int p = 0; p < 8; p++) res[p] = 0.0f;

#pragma unroll
    for (int so = 0; so < 4; so++) {
        float4 xa = *(const float4*)(x + so * 1048576 + base_sp);
        float4 xb = *(const float4*)(x + so * 1048576 + base_sp + 4);
        float xs[8] = {xa.x, xa.y, xa.z, xa.w, xb.x, xb.y, xb.z, xb.w};
#pragma unroll
        for (int p = 0; p < 8; p++) {
            float s1 = 1.0f / (1.0f + __expf(-acc[p][so][0]));
            float s2 = 1.0f / (1.0f + __expf(-acc[p][so][1]));
            res[p] += (xs[p] != 0.0f) ? (s1 + s2) : 0.0f;
        }
    }
    *(float4*)(out + base_sp)     = make_float4(res[0], res[1], res[2], res[3]);
    *(float4*)(out + base_sp + 4) = make_float4(res[4], res[5], res[6], res[7]);
}

extern "C" void kernel_launch(void* const* d_in, const int* in_sizes, int n_in,
                              void* d_out, int out_size) {
    const float* x    = (const float*)d_in[0];   // (1,2,2,32,32,32,32)
    const float* kern = (const float*)d_in[1];   // (729,)
    float* out = (float*)d_out;                  // (1,32,32,32,32)

    prep_kernel<<<3, 256>>>(kern);

    cudaFuncSetAttribute(conv_kernel,
                         cudaFuncAttributeMaxDynamicSharedMemorySize, SMEM_BYTES);
    conv_kernel<<<1024, 128, SMEM_BYTES>>>(x, out);
}